// round 10
// baseline (speedup 1.0000x reference)
#include <cuda_runtime.h>
#include <cuda_fp16.h>
#include <cstdint>

#define NN 100000
#define EE 1600000
#define HH 128
#define GG 512
#define BN_EPS 1e-5f
#define SCAN_B 1024
#define NB ((NN + SCAN_B - 1) / SCAN_B)   // 98 scan blocks

// ---------------- scratch (device globals: no allocation allowed) -----------
__device__ __half g_t[(size_t)NN * HH];   // t' ping buffer (fp16)
__device__ __half g_h[(size_t)NN * HH];   // t' pong buffer (fp16)
__device__ __half g_Wh[3 * HH * HH];      // BN-folded fp16 weights
__device__ float  g_beta[3 * HH];         // BN-folded shifts
__device__ float  g_dinv[NN];
__device__ int    g_deg[NN];
__device__ int    g_rowptr[NN + 1];
__device__ int    g_cursor[NN];
__device__ int    g_col[EE];
__device__ float  g_gsum[GG];
__device__ int    g_gcnt[GG];
__device__ int    g_part[NB];

__device__ __forceinline__ uint32_t s2u(const void* p) {
    return (uint32_t)__cvta_generic_to_shared(p);
}

// ---------------- preprocessing kernels ------------------------------------
__global__ void k_zero() {
    int i = blockIdx.x * blockDim.x + threadIdx.x;
    if (i < NN) g_deg[i] = 0;
    if (i < GG) { g_gsum[i] = 0.0f; g_gcnt[i] = 0; }
}

__global__ void k_hist(const int* __restrict__ ei, const int* __restrict__ batch) {
    int e = blockIdx.x * blockDim.x + threadIdx.x;
    if (e < EE) atomicAdd(&g_deg[ei[EE + e]], 1);
    if (e < NN) atomicAdd(&g_gcnt[batch[e]], 1);
}

__global__ void k_scan_local() {
    __shared__ int sh[SCAN_B];
    int tx = threadIdx.x;
    int i = blockIdx.x * SCAN_B + tx;
    int v = (i < NN) ? g_deg[i] : 0;
    if (i < NN) g_dinv[i] = rsqrtf((float)(v + 1));   // fused dinv (+1 self-loop)
    sh[tx] = v;
    __syncthreads();
    for (int off = 1; off < SCAN_B; off <<= 1) {
        int t = (tx >= off) ? sh[tx - off] : 0;
        __syncthreads();
        sh[tx] += t;
        __syncthreads();
    }
    if (i < NN) g_rowptr[i] = sh[tx] - v;        // exclusive
    if (tx == SCAN_B - 1) g_part[blockIdx.x] = sh[tx];
}

__global__ void k_scan_part() {
    __shared__ int sh[128];
    int tx = threadIdx.x;
    int v = (tx < NB) ? g_part[tx] : 0;
    sh[tx] = v;
    __syncthreads();
    for (int off = 1; off < 128; off <<= 1) {
        int t = (tx >= off) ? sh[tx - off] : 0;
        __syncthreads();
        sh[tx] += t;
        __syncthreads();
    }
    if (tx < NB) g_part[tx] = sh[tx] - v;        // exclusive block offsets
}

__global__ void k_scan_add() {
    int i = blockIdx.x * blockDim.x + threadIdx.x;
    if (i < NN) {
        int v = g_rowptr[i] + g_part[i >> 10];
        g_rowptr[i] = v;
        g_cursor[i] = v;
    }
    if (i == 0) g_rowptr[NN] = EE;
}

__global__ void k_fill(const int* __restrict__ ei) {
    int e = blockIdx.x * blockDim.x + threadIdx.x;
    if (e < EE) {
        int src = ei[e];
        int dst = ei[EE + e];
        int p = atomicAdd(&g_cursor[dst], 1);
        g_col[p] = src;
    }
}

// Fold BN scale into W columns (fp16) for all 3 layers, compute folded shifts.
__global__ void k_prep_w(const float* __restrict__ W1v, const float* __restrict__ W2v,
                         const float* __restrict__ W3v,
                         const float* __restrict__ b1v, const float* __restrict__ b2v,
                         const float* __restrict__ b3v,
                         const float* __restrict__ ga1, const float* __restrict__ ga2,
                         const float* __restrict__ ga3,
                         const float* __restrict__ be1, const float* __restrict__ be2,
                         const float* __restrict__ be3,
                         const float* __restrict__ m1v, const float* __restrict__ m2v,
                         const float* __restrict__ m3v,
                         const float* __restrict__ v1v, const float* __restrict__ v2v,
                         const float* __restrict__ v3v) {
    int layer = blockIdx.y;
    const float* W  = layer == 0 ? W1v : layer == 1 ? W2v : W3v;
    const float* b  = layer == 0 ? b1v : layer == 1 ? b2v : b3v;
    const float* ga = layer == 0 ? ga1 : layer == 1 ? ga2 : ga3;
    const float* be = layer == 0 ? be1 : layer == 1 ? be2 : be3;
    const float* m  = layer == 0 ? m1v : layer == 1 ? m2v : m3v;
    const float* v  = layer == 0 ? v1v : layer == 1 ? v2v : v3v;
    int idx = blockIdx.x * blockDim.x + threadIdx.x;
    if (idx < HH * HH) {
        int n = idx & (HH - 1);
        float alpha = ga[n] * rsqrtf(v[n] + BN_EPS);
        g_Wh[layer * HH * HH + idx] = __float2half(W[idx] * alpha);
    }
    if (idx < HH) {
        float alpha = ga[idx] * rsqrtf(v[idx] + BN_EPS);
        g_beta[layer * HH + idx] = (b[idx] - m[idx]) * alpha + be[idx];
    }
}

// ---------------- shared agg helper: acc[8] = t'[node] + sum_src t'[src] ----
__device__ __forceinline__ void agg_row(const uint4* __restrict__ T, int node,
                                        int sub, float* acc) {
    uint4 u = T[(size_t)node * 16 + sub];
    {
        const __half2* p = (const __half2*)&u;
#pragma unroll
        for (int q = 0; q < 4; q++) {
            float2 f = __half22float2(p[q]);
            acc[q * 2] = f.x; acc[q * 2 + 1] = f.y;
        }
    }
    int e = g_rowptr[node];
    int e1 = g_rowptr[node + 1];
    for (; e + 8 <= e1; e += 8) {
        int s[8];
        uint4 v[8];
#pragma unroll
        for (int j = 0; j < 8; j++) s[j] = __ldg(&g_col[e + j]);
#pragma unroll
        for (int j = 0; j < 8; j++) v[j] = T[(size_t)s[j] * 16 + sub];
#pragma unroll
        for (int j = 0; j < 8; j++) {
            const __half2* p = (const __half2*)&v[j];
#pragma unroll
            for (int q = 0; q < 4; q++) {
                float2 f = __half22float2(p[q]);
                acc[q * 2] += f.x; acc[q * 2 + 1] += f.y;
            }
        }
    }
    for (; e + 4 <= e1; e += 4) {
        int s[4];
        uint4 v[4];
#pragma unroll
        for (int j = 0; j < 4; j++) s[j] = __ldg(&g_col[e + j]);
#pragma unroll
        for (int j = 0; j < 4; j++) v[j] = T[(size_t)s[j] * 16 + sub];
#pragma unroll
        for (int j = 0; j < 4; j++) {
            const __half2* p = (const __half2*)&v[j];
#pragma unroll
            for (int q = 0; q < 4; q++) {
                float2 f = __half22float2(p[q]);
                acc[q * 2] += f.x; acc[q * 2 + 1] += f.y;
            }
        }
    }
    for (; e < e1; ++e) {
        int s = __ldg(&g_col[e]);
        uint4 v = T[(size_t)s * 16 + sub];
        const __half2* p = (const __half2*)&v;
#pragma unroll
        for (int q = 0; q < 4; q++) {
            float2 f = __half22float2(p[q]);
            acc[q * 2] += f.x; acc[q * 2 + 1] += f.y;
        }
    }
}

// ---------------- layer-1 GEMM (fp32 input): t' = dinv .* (X @ W1') --------
__global__ void __launch_bounds__(256) k_gemm_tc(const float* __restrict__ Xv,
                                                 const __half* __restrict__ W,
                                                 __half* __restrict__ Y) {
    extern __shared__ __half sh[];
    __half* As = sh;               // 128 x 136
    __half* Ws = sh + 128 * 136;

    int tid = threadIdx.x;
    int row0 = blockIdx.x * 128;

    const uint4* Wg = (const uint4*)W;
#pragma unroll
    for (int i = 0; i < 8; i++) {
        int idx = i * 256 + tid;
        int r = idx >> 4, c = (idx & 15) * 8;
        *(uint4*)&Ws[r * 136 + c] = Wg[idx];
    }
    const float4* Xg = (const float4*)Xv;
#pragma unroll
    for (int i = 0; i < 16; i++) {
        int idx = i * 256 + tid;
        int r = idx >> 5, c = (idx & 31) * 4;
        float4 v = make_float4(0.f, 0.f, 0.f, 0.f);
        if (row0 + r < NN) v = Xg[(size_t)(row0 + r) * 32 + (idx & 31)];
        *(__half2*)&As[r * 136 + c]     = __floats2half2_rn(v.x, v.y);
        *(__half2*)&As[r * 136 + c + 2] = __floats2half2_rn(v.z, v.w);
    }
    __syncthreads();

    int wid = tid >> 5, lane = tid & 31;
    int m0 = wid * 16;

    float acc[16][4];
#pragma unroll
    for (int nt = 0; nt < 16; nt++)
#pragma unroll
        for (int c = 0; c < 4; c++) acc[nt][c] = 0.f;

#pragma unroll
    for (int ks = 0; ks < 8; ks++) {
        uint32_t a0, a1, a2, a3;
        uint32_t aaddr = s2u(&As[(m0 + (lane & 15)) * 136 + ks * 16 + (lane >> 4) * 8]);
        asm volatile("ldmatrix.sync.aligned.m8n8.x4.shared.b16 {%0,%1,%2,%3}, [%4];"
                     : "=r"(a0), "=r"(a1), "=r"(a2), "=r"(a3) : "r"(aaddr));
#pragma unroll
        for (int ng = 0; ng < 8; ng++) {
            uint32_t b0, b1, b2, b3;
            uint32_t baddr = s2u(&Ws[(ks * 16 + (lane & 15)) * 136 +
                                     ng * 16 + (lane >> 4) * 8]);
            asm volatile("ldmatrix.sync.aligned.m8n8.x4.trans.shared.b16 {%0,%1,%2,%3}, [%4];"
                         : "=r"(b0), "=r"(b1), "=r"(b2), "=r"(b3) : "r"(baddr));
            int nt = ng * 2;
            asm volatile(
                "mma.sync.aligned.m16n8k16.row.col.f32.f16.f16.f32 "
                "{%0,%1,%2,%3}, {%4,%5,%6,%7}, {%8,%9}, {%0,%1,%2,%3};"
                : "+f"(acc[nt][0]), "+f"(acc[nt][1]), "+f"(acc[nt][2]), "+f"(acc[nt][3])
                : "r"(a0), "r"(a1), "r"(a2), "r"(a3), "r"(b0), "r"(b1));
            asm volatile(
                "mma.sync.aligned.m16n8k16.row.col.f32.f16.f16.f32 "
                "{%0,%1,%2,%3}, {%4,%5,%6,%7}, {%8,%9}, {%0,%1,%2,%3};"
                : "+f"(acc[nt + 1][0]), "+f"(acc[nt + 1][1]), "+f"(acc[nt + 1][2]), "+f"(acc[nt + 1][3])
                : "r"(a0), "r"(a1), "r"(a2), "r"(a3), "r"(b2), "r"(b3));
        }
    }

    int r0 = row0 + m0 + (lane >> 2);
    int cb = (lane & 3) * 2;
    float d0 = (r0 < NN) ? g_dinv[r0] : 0.f;
    float d1 = (r0 + 8 < NN) ? g_dinv[r0 + 8] : 0.f;
#pragma unroll
    for (int nt = 0; nt < 16; nt++) {
        if (r0 < NN)
            *(__half2*)&Y[(size_t)r0 * 128 + nt * 8 + cb] =
                __floats2half2_rn(acc[nt][0] * d0, acc[nt][1] * d0);
        if (r0 + 8 < NN)
            *(__half2*)&Y[(size_t)(r0 + 8) * 128 + nt * 8 + cb] =
                __floats2half2_rn(acc[nt][2] * d1, acc[nt][3] * d1);
    }
}

// ---------------- FUSED: agg(L) + BN/ReLU + GEMM(L+1) + dinv ---------------
// Block b aggregates nodes [128b,128b+128) from Tin straight into the A smem
// tile (h never hits gmem), then computes Tout = dinv .* (h @ Wnext).
// W is cp.async'd during the agg phase.
__global__ void __launch_bounds__(256, 2) k_fused(const __half* __restrict__ Tin,
                                                  __half* __restrict__ Tout,
                                                  const float* __restrict__ beta,
                                                  const __half* __restrict__ Wnext) {
    extern __shared__ __half sh[];
    __half* As = sh;               // h tile 128 x 136
    __half* Ws = sh + 128 * 136;

    int tid = threadIdx.x;
    int row0 = blockIdx.x * 128;

    // async W load (2048 x 16B), overlapped with aggregation below
    {
        const char* Wg = (const char*)Wnext;
#pragma unroll
        for (int i = 0; i < 8; i++) {
            int idx = i * 256 + tid;
            int r = idx >> 4, ch = idx & 15;
            uint32_t saddr = s2u(&Ws[0]) + r * 272 + ch * 16;
            asm volatile("cp.async.cg.shared.global [%0], [%1], 16;"
                         :: "r"(saddr), "l"(Wg + (size_t)r * 256 + ch * 16));
        }
        asm volatile("cp.async.commit_group;");
    }

    int wid = tid >> 5, lane = tid & 31;
    int half = lane >> 4, sub = lane & 15;
    const uint4* T = (const uint4*)Tin;

    // agg phase: each warp produces 16 h-rows (2 per iteration, half-warp each)
    for (int it = 0; it < 8; it++) {
        int local = wid * 16 + it * 2 + half;
        int node = row0 + local;
        uint4 o = make_uint4(0, 0, 0, 0);
        if (node < NN) {
            float acc[8];
            agg_row(T, node, sub, acc);
            float di = g_dinv[node];
            float4 be0 = ((const float4*)beta)[sub * 2];
            float4 be1 = ((const float4*)beta)[sub * 2 + 1];
            __half2* p = (__half2*)&o;
            p[0] = __floats2half2_rn(fmaxf(0.f, fmaf(di, acc[0], be0.x)),
                                     fmaxf(0.f, fmaf(di, acc[1], be0.y)));
            p[1] = __floats2half2_rn(fmaxf(0.f, fmaf(di, acc[2], be0.z)),
                                     fmaxf(0.f, fmaf(di, acc[3], be0.w)));
            p[2] = __floats2half2_rn(fmaxf(0.f, fmaf(di, acc[4], be1.x)),
                                     fmaxf(0.f, fmaf(di, acc[5], be1.y)));
            p[3] = __floats2half2_rn(fmaxf(0.f, fmaf(di, acc[6], be1.z)),
                                     fmaxf(0.f, fmaf(di, acc[7], be1.w)));
        }
        *(uint4*)&As[local * 136 + sub * 8] = o;
    }
    asm volatile("cp.async.wait_group 0;");
    __syncthreads();

    // GEMM phase
    int m0 = wid * 16;
    float acc[16][4];
#pragma unroll
    for (int nt = 0; nt < 16; nt++)
#pragma unroll
        for (int c = 0; c < 4; c++) acc[nt][c] = 0.f;

#pragma unroll
    for (int ks = 0; ks < 8; ks++) {
        uint32_t a0, a1, a2, a3;
        uint32_t aaddr = s2u(&As[(m0 + (lane & 15)) * 136 + ks * 16 + (lane >> 4) * 8]);
        asm volatile("ldmatrix.sync.aligned.m8n8.x4.shared.b16 {%0,%1,%2,%3}, [%4];"
                     : "=r"(a0), "=r"(a1), "=r"(a2), "=r"(a3) : "r"(aaddr));
#pragma unroll
        for (int ng = 0; ng < 8; ng++) {
            uint32_t b0, b1, b2, b3;
            uint32_t baddr = s2u(&Ws[(ks * 16 + (lane & 15)) * 136 +
                                     ng * 16 + (lane >> 4) * 8]);
            asm volatile("ldmatrix.sync.aligned.m8n8.x4.trans.shared.b16 {%0,%1,%2,%3}, [%4];"
                         : "=r"(b0), "=r"(b1), "=r"(b2), "=r"(b3) : "r"(baddr));
            int nt = ng * 2;
            asm volatile(
                "mma.sync.aligned.m16n8k16.row.col.f32.f16.f16.f32 "
                "{%0,%1,%2,%3}, {%4,%5,%6,%7}, {%8,%9}, {%0,%1,%2,%3};"
                : "+f"(acc[nt][0]), "+f"(acc[nt][1]), "+f"(acc[nt][2]), "+f"(acc[nt][3])
                : "r"(a0), "r"(a1), "r"(a2), "r"(a3), "r"(b0), "r"(b1));
            asm volatile(
                "mma.sync.aligned.m16n8k16.row.col.f32.f16.f16.f32 "
                "{%0,%1,%2,%3}, {%4,%5,%6,%7}, {%8,%9}, {%0,%1,%2,%3};"
                : "+f"(acc[nt + 1][0]), "+f"(acc[nt + 1][1]), "+f"(acc[nt + 1][2]), "+f"(acc[nt + 1][3])
                : "r"(a0), "r"(a1), "r"(a2), "r"(a3), "r"(b2), "r"(b3));
        }
    }

    int r0 = row0 + m0 + (lane >> 2);
    int cb = (lane & 3) * 2;
    float d0 = (r0 < NN) ? g_dinv[r0] : 0.f;
    float d1 = (r0 + 8 < NN) ? g_dinv[r0 + 8] : 0.f;
#pragma unroll
    for (int nt = 0; nt < 16; nt++) {
        if (r0 < NN)
            *(__half2*)&Tout[(size_t)r0 * 128 + nt * 8 + cb] =
                __floats2half2_rn(acc[nt][0] * d0, acc[nt][1] * d0);
        if (r0 + 8 < NN)
            *(__half2*)&Tout[(size_t)(r0 + 8) * 128 + nt * 8 + cb] =
                __floats2half2_rn(acc[nt][2] * d1, acc[nt][3] * d1);
    }
}

// ---------------- final aggregation + mean-pool + linear head --------------
// reads g_t (layer-3 t'), reduces per-node dot with Wl into g_gsum.
__global__ void __launch_bounds__(256) k_agg_final(const float* __restrict__ beta,
                                                   const float* __restrict__ Wl,
                                                   const int* __restrict__ batch) {
    int warp = (blockIdx.x * blockDim.x + threadIdx.x) >> 5;
    int lane = threadIdx.x & 31;
    int half = lane >> 4;
    int sub = lane & 15;
    int node = warp * 2 + half;
    if (node >= NN) return;

    float acc[8];
    agg_row((const uint4*)g_t, node, sub, acc);

    float di = g_dinv[node];
    float4 be0 = ((const float4*)beta)[sub * 2];
    float4 be1 = ((const float4*)beta)[sub * 2 + 1];
    float4 wl0 = ((const float4*)Wl)[sub * 2];
    float4 wl1 = ((const float4*)Wl)[sub * 2 + 1];
    float s =
        fmaxf(0.f, fmaf(di, acc[0], be0.x)) * wl0.x +
        fmaxf(0.f, fmaf(di, acc[1], be0.y)) * wl0.y +
        fmaxf(0.f, fmaf(di, acc[2], be0.z)) * wl0.z +
        fmaxf(0.f, fmaf(di, acc[3], be0.w)) * wl0.w +
        fmaxf(0.f, fmaf(di, acc[4], be1.x)) * wl1.x +
        fmaxf(0.f, fmaf(di, acc[5], be1.y)) * wl1.y +
        fmaxf(0.f, fmaf(di, acc[6], be1.z)) * wl1.z +
        fmaxf(0.f, fmaf(di, acc[7], be1.w)) * wl1.w;
    unsigned mask = half ? 0xFFFF0000u : 0x0000FFFFu;
#pragma unroll
    for (int off = 8; off > 0; off >>= 1)
        s += __shfl_xor_sync(mask, s, off);
    if (sub == 0) atomicAdd(&g_gsum[batch[node]], s);
}

__global__ void k_final(float* __restrict__ out, const float* __restrict__ bl) {
    int g = blockIdx.x * blockDim.x + threadIdx.x;
    if (g < GG) out[g] = g_gsum[g] / fmaxf((float)g_gcnt[g], 1.0f) + bl[0];
}

// ---------------- host launcher --------------------------------------------
extern "C" void kernel_launch(void* const* d_in, const int* in_sizes, int n_in,
                              void* d_out, int out_size) {
    const float* x     = (const float*)d_in[0];
    const int*   ei    = (const int*)d_in[1];
    const int*   batch = (const int*)d_in[2];
    const float* W1 = (const float*)d_in[3];
    const float* b1 = (const float*)d_in[4];
    const float* g1 = (const float*)d_in[5];
    const float* be1 = (const float*)d_in[6];
    const float* m1 = (const float*)d_in[7];
    const float* v1 = (const float*)d_in[8];
    const float* W2 = (const float*)d_in[9];
    const float* b2 = (const float*)d_in[10];
    const float* g2 = (const float*)d_in[11];
    const float* be2 = (const float*)d_in[12];
    const float* m2 = (const float*)d_in[13];
    const float* v2 = (const float*)d_in[14];
    const float* W3 = (const float*)d_in[15];
    const float* b3 = (const float*)d_in[16];
    const float* g3 = (const float*)d_in[17];
    const float* be3 = (const float*)d_in[18];
    const float* m3 = (const float*)d_in[19];
    const float* v3 = (const float*)d_in[20];
    const float* Wl = (const float*)d_in[21];
    const float* bl = (const float*)d_in[22];

    __half *t, *h, *Wh;
    float *beta;
    cudaGetSymbolAddress((void**)&t, g_t);
    cudaGetSymbolAddress((void**)&h, g_h);
    cudaGetSymbolAddress((void**)&Wh, g_Wh);
    cudaGetSymbolAddress((void**)&beta, g_beta);

    const int GEMM_SMEM = 2 * 128 * 136 * (int)sizeof(__half);   // 69632
    cudaFuncSetAttribute(k_gemm_tc, cudaFuncAttributeMaxDynamicSharedMemorySize, GEMM_SMEM);
    cudaFuncSetAttribute(k_fused,   cudaFuncAttributeMaxDynamicSharedMemorySize, GEMM_SMEM);

    static cudaStream_t s1 = nullptr;
    static cudaEvent_t evStart = nullptr, evDinv = nullptr, evG1 = nullptr;
    if (s1 == nullptr) {
        cudaStreamCreateWithFlags(&s1, cudaStreamNonBlocking);
        cudaEventCreateWithFlags(&evStart, cudaEventDisableTiming);
        cudaEventCreateWithFlags(&evDinv, cudaEventDisableTiming);
        cudaEventCreateWithFlags(&evG1, cudaEventDisableTiming);
    }

    const int TPB = 256;
    const int GEMM_BLOCKS = (NN + 127) / 128;                    // 782
    const int AGG_BLOCKS = ((NN + 1) / 2 * 32 + TPB - 1) / TPB;  // 6250

    // ---- fork: side stream handles weight prep (input-only dependency)
    cudaEventRecord(evStart, 0);
    cudaStreamWaitEvent(s1, evStart, 0);
    {
        dim3 grid(64, 3);
        k_prep_w<<<grid, 256, 0, s1>>>(W1, W2, W3, b1, b2, b3, g1, g2, g3,
                                       be1, be2, be3, m1, m2, m3, v1, v2, v3);
    }

    // ---- main stream: graph preprocessing
    k_zero<<<(NN + TPB - 1) / TPB, TPB>>>();
    k_hist<<<(EE + TPB - 1) / TPB, TPB>>>(ei, batch);
    k_scan_local<<<NB, SCAN_B>>>();                     // produces dinv
    cudaEventRecord(evDinv, 0);
    k_scan_part<<<1, 128>>>();
    k_scan_add<<<(NN + TPB) / TPB, TPB>>>();
    k_fill<<<(EE + TPB - 1) / TPB, TPB>>>(ei);

    // ---- side stream: gemm1 (needs Wh + dinv), overlaps scan/fill
    cudaStreamWaitEvent(s1, evDinv, 0);
    k_gemm_tc<<<GEMM_BLOCKS, 256, GEMM_SMEM, s1>>>(x, Wh, t);
    cudaEventRecord(evG1, s1);

    // ---- join, then fused layers
    cudaStreamWaitEvent(0, evG1, 0);
    // layer-1 agg + layer-2 GEMM (t -> h)
    k_fused<<<GEMM_BLOCKS, 256, GEMM_SMEM>>>(t, h, beta, Wh + HH * HH);
    // layer-2 agg + layer-3 GEMM (h -> t)
    k_fused<<<GEMM_BLOCKS, 256, GEMM_SMEM>>>(h, t, beta + HH, Wh + 2 * HH * HH);
    // layer-3 agg + mean-pool + linear head (reads t)
    k_agg_final<<<AGG_BLOCKS, TPB>>>(beta + 2 * HH, Wl, batch);

    k_final<<<(GG + TPB - 1) / TPB, TPB>>>((float*)d_out, bl);
}

// round 11
// speedup vs baseline: 1.1373x; 1.1373x over previous
#include <cuda_runtime.h>
#include <cuda_fp16.h>
#include <cstdint>

#define NN 100000
#define EE 1600000
#define HH 128
#define GG 512
#define BN_EPS 1e-5f
#define SCAN_B 1024
#define NB ((NN + SCAN_B - 1) / SCAN_B)   // 98 scan blocks

// ---------------- scratch (device globals: no allocation allowed) -----------
__device__ __half g_t[(size_t)NN * HH];   // GEMM output t' = dinv .* (h @ W') (fp16)
__device__ __half g_h[(size_t)NN * HH];   // activated hidden (fp16)
__device__ __half g_Wh[3 * HH * HH];      // BN-folded fp16 weights
__device__ float  g_beta[3 * HH];         // BN-folded shifts
__device__ float  g_dinv[NN];
__device__ int    g_deg[NN];
__device__ int    g_rowptr[NN];           // block-LOCAL exclusive scan
__device__ int    g_cursor[NN];           // block-LOCAL fill cursor
__device__ int    g_col[EE];
__device__ float  g_gsum[GG];
__device__ int    g_gcnt[GG];
__device__ int    g_part[NB];             // per-block offsets (exclusive)
__device__ int    g_done;

__device__ __forceinline__ uint32_t s2u(const void* p) {
    return (uint32_t)__cvta_generic_to_shared(p);
}

// ---------------- preprocessing kernels ------------------------------------
__global__ void k_zero() {
    int i = blockIdx.x * blockDim.x + threadIdx.x;
    if (i < NN) g_deg[i] = 0;
    if (i < GG) { g_gsum[i] = 0.0f; g_gcnt[i] = 0; }
    if (i == 0) g_done = 0;
}

__global__ void k_hist(const int* __restrict__ ei, const int* __restrict__ batch) {
    int e = blockIdx.x * blockDim.x + threadIdx.x;
    if (e < EE) atomicAdd(&g_deg[ei[EE + e]], 1);
    if (e < NN) atomicAdd(&g_gcnt[batch[e]], 1);
}

__global__ void k_scan_local() {
    __shared__ int sh[SCAN_B];
    int tx = threadIdx.x;
    int i = blockIdx.x * SCAN_B + tx;
    int v = (i < NN) ? g_deg[i] : 0;
    if (i < NN) g_dinv[i] = rsqrtf((float)(v + 1));   // fused dinv (+1 self-loop)
    sh[tx] = v;
    __syncthreads();
    for (int off = 1; off < SCAN_B; off <<= 1) {
        int t = (tx >= off) ? sh[tx - off] : 0;
        __syncthreads();
        sh[tx] += t;
        __syncthreads();
    }
    if (i < NN) {
        int ex = sh[tx] - v;          // local exclusive
        g_rowptr[i] = ex;
        g_cursor[i] = ex;
    }
    if (tx == SCAN_B - 1) g_part[blockIdx.x] = sh[tx];
}

__global__ void k_scan_part() {
    __shared__ int sh[128];
    int tx = threadIdx.x;
    int v = (tx < NB) ? g_part[tx] : 0;
    sh[tx] = v;
    __syncthreads();
    for (int off = 1; off < 128; off <<= 1) {
        int t = (tx >= off) ? sh[tx - off] : 0;
        __syncthreads();
        sh[tx] += t;
        __syncthreads();
    }
    if (tx < NB) g_part[tx] = sh[tx] - v;        // exclusive block offsets
}

__global__ void k_fill(const int* __restrict__ ei) {
    int e = blockIdx.x * blockDim.x + threadIdx.x;
    if (e < EE) {
        int src = ei[e];
        int dst = ei[EE + e];
        int p = atomicAdd(&g_cursor[dst], 1) + g_part[dst >> 10];
        g_col[p] = src;
    }
}

// Fold BN scale into W columns (fp16) for all 3 layers, compute folded shifts.
__global__ void k_prep_w(const float* __restrict__ W1v, const float* __restrict__ W2v,
                         const float* __restrict__ W3v,
                         const float* __restrict__ b1v, const float* __restrict__ b2v,
                         const float* __restrict__ b3v,
                         const float* __restrict__ ga1, const float* __restrict__ ga2,
                         const float* __restrict__ ga3,
                         const float* __restrict__ be1, const float* __restrict__ be2,
                         const float* __restrict__ be3,
                         const float* __restrict__ m1v, const float* __restrict__ m2v,
                         const float* __restrict__ m3v,
                         const float* __restrict__ v1v, const float* __restrict__ v2v,
                         const float* __restrict__ v3v) {
    int layer = blockIdx.y;
    const float* W  = layer == 0 ? W1v : layer == 1 ? W2v : W3v;
    const float* b  = layer == 0 ? b1v : layer == 1 ? b2v : b3v;
    const float* ga = layer == 0 ? ga1 : layer == 1 ? ga2 : ga3;
    const float* be = layer == 0 ? be1 : layer == 1 ? be2 : be3;
    const float* m  = layer == 0 ? m1v : layer == 1 ? m2v : m3v;
    const float* v  = layer == 0 ? v1v : layer == 1 ? v2v : v3v;
    int idx = blockIdx.x * blockDim.x + threadIdx.x;
    if (idx < HH * HH) {
        int n = idx & (HH - 1);
        float alpha = ga[n] * rsqrtf(v[n] + BN_EPS);
        g_Wh[layer * HH * HH + idx] = __float2half(W[idx] * alpha);
    }
    if (idx < HH) {
        float alpha = ga[idx] * rsqrtf(v[idx] + BN_EPS);
        g_beta[layer * HH + idx] = (b[idx] - m[idx]) * alpha + be[idx];
    }
}

// ---------------- fp16 tensor-core GEMM + dinv prescale epilogue -----------
// Y[i,:] = dinv[i] * (X[i,:] @ W).
// F32IN: bulk sync loads (with f32->f16 convert). !F32IN: cp.async 2-stage
// K-split: stage h = A k-columns [h*64,..) (byte-half of A rows) + W k-ROWS
// [h*64,..) (full 256B rows). Stage-0 compute overlaps stage-1 copies.
template <bool F32IN>
__global__ void __launch_bounds__(256) k_gemm_tc(const void* __restrict__ Xv,
                                                 const __half* __restrict__ W,
                                                 __half* __restrict__ Y) {
    extern __shared__ __half sh[];
    __half* As = sh;               // 128 x 136 (272 B pitch)
    __half* Ws = sh + 128 * 136;   // 128 x 136 (row = k, cols = n)

    int tid = threadIdx.x;
    int row0 = blockIdx.x * 128;

    if (F32IN) {
        const uint4* Wg = (const uint4*)W;
#pragma unroll
        for (int i = 0; i < 8; i++) {
            int idx = i * 256 + tid;
            int r = idx >> 4, c = (idx & 15) * 8;
            *(uint4*)&Ws[r * 136 + c] = Wg[idx];
        }
        const float4* Xg = (const float4*)Xv;
#pragma unroll
        for (int i = 0; i < 16; i++) {
            int idx = i * 256 + tid;
            int r = idx >> 5, c = (idx & 31) * 4;
            float4 v = make_float4(0.f, 0.f, 0.f, 0.f);
            if (row0 + r < NN) v = Xg[(size_t)(row0 + r) * 32 + (idx & 31)];
            *(__half2*)&As[r * 136 + c]     = __floats2half2_rn(v.x, v.y);
            *(__half2*)&As[r * 136 + c + 2] = __floats2half2_rn(v.z, v.w);
        }
        __syncthreads();
    } else {
        const char* Ag = (const char*)Xv;     // 256 B per row (k bytes)
        const char* Wg = (const char*)W;      // 256 B per row (row = k, bytes = n)
#pragma unroll
        for (int h = 0; h < 2; h++) {
#pragma unroll
            for (int i = 0; i < 4; i++) {     // A: 1024 chunks
                int idx = i * 256 + tid;
                int r = idx >> 3, ch = idx & 7;
                uint32_t saddr = s2u(&As[0]) + r * 272 + h * 128 + ch * 16;
                const char* gaddr = Ag + (size_t)(row0 + r) * 256 + h * 128 + ch * 16;
                int sz = (row0 + r < NN) ? 16 : 0;
                asm volatile("cp.async.cg.shared.global [%0], [%1], 16, %2;"
                             :: "r"(saddr), "l"(gaddr), "r"(sz));
            }
#pragma unroll
            for (int i = 0; i < 4; i++) {     // W: 64 rows x 16 chunks
                int idx = i * 256 + tid;
                int r = h * 64 + (idx >> 4);
                int ch = idx & 15;
                uint32_t saddr = s2u(&Ws[0]) + r * 272 + ch * 16;
                const char* gaddr = Wg + (size_t)r * 256 + ch * 16;
                asm volatile("cp.async.cg.shared.global [%0], [%1], 16;"
                             :: "r"(saddr), "l"(gaddr));
            }
            asm volatile("cp.async.commit_group;");
        }
    }

    int wid = tid >> 5, lane = tid & 31;
    int m0 = wid * 16;

    float acc[16][4];
#pragma unroll
    for (int nt = 0; nt < 16; nt++)
#pragma unroll
        for (int c = 0; c < 4; c++) acc[nt][c] = 0.f;

#pragma unroll
    for (int h = 0; h < 2; h++) {
        if (!F32IN) {
            if (h == 0) { asm volatile("cp.async.wait_group 1;"); }
            else        { asm volatile("cp.async.wait_group 0;"); }
            __syncthreads();
        }
#pragma unroll
        for (int ksl = 0; ksl < 4; ksl++) {
            int ks = h * 4 + ksl;
            uint32_t a0, a1, a2, a3;
            uint32_t aaddr = s2u(&As[(m0 + (lane & 15)) * 136 + ks * 16 + (lane >> 4) * 8]);
            asm volatile("ldmatrix.sync.aligned.m8n8.x4.shared.b16 {%0,%1,%2,%3}, [%4];"
                         : "=r"(a0), "=r"(a1), "=r"(a2), "=r"(a3) : "r"(aaddr));
#pragma unroll
            for (int ng = 0; ng < 8; ng++) {
                uint32_t b0, b1, b2, b3;
                uint32_t baddr = s2u(&Ws[(ks * 16 + (lane & 15)) * 136 +
                                         ng * 16 + (lane >> 4) * 8]);
                asm volatile("ldmatrix.sync.aligned.m8n8.x4.trans.shared.b16 {%0,%1,%2,%3}, [%4];"
                             : "=r"(b0), "=r"(b1), "=r"(b2), "=r"(b3) : "r"(baddr));
                int nt = ng * 2;
                asm volatile(
                    "mma.sync.aligned.m16n8k16.row.col.f32.f16.f16.f32 "
                    "{%0,%1,%2,%3}, {%4,%5,%6,%7}, {%8,%9}, {%0,%1,%2,%3};"
                    : "+f"(acc[nt][0]), "+f"(acc[nt][1]), "+f"(acc[nt][2]), "+f"(acc[nt][3])
                    : "r"(a0), "r"(a1), "r"(a2), "r"(a3), "r"(b0), "r"(b1));
                asm volatile(
                    "mma.sync.aligned.m16n8k16.row.col.f32.f16.f16.f32 "
                    "{%0,%1,%2,%3}, {%4,%5,%6,%7}, {%8,%9}, {%0,%1,%2,%3};"
                    : "+f"(acc[nt + 1][0]), "+f"(acc[nt + 1][1]), "+f"(acc[nt + 1][2]), "+f"(acc[nt + 1][3])
                    : "r"(a0), "r"(a1), "r"(a2), "r"(a3), "r"(b2), "r"(b3));
            }
        }
    }

    int r0 = row0 + m0 + (lane >> 2);
    int cb = (lane & 3) * 2;
    float d0 = (r0 < NN) ? g_dinv[r0] : 0.f;
    float d1 = (r0 + 8 < NN) ? g_dinv[r0 + 8] : 0.f;
#pragma unroll
    for (int nt = 0; nt < 16; nt++) {
        if (r0 < NN)
            *(__half2*)&Y[(size_t)r0 * 128 + nt * 8 + cb] =
                __floats2half2_rn(acc[nt][0] * d0, acc[nt][1] * d0);
        if (r0 + 8 < NN)
            *(__half2*)&Y[(size_t)(r0 + 8) * 128 + nt * 8 + cb] =
                __floats2half2_rn(acc[nt][2] * d1, acc[nt][3] * d1);
    }
}

// ---------------- aggregation + folded-BN + ReLU (2 nodes per warp) --------
// 16 lanes x uint4 (LDG.128) per node row. t' pre-scaled by dinv[src].
// FINAL: fused mean-pool + linear head + last-block output write.
template <bool FINAL>
__global__ void __launch_bounds__(256) k_agg16(const float* __restrict__ beta,
                                               const float* __restrict__ Wl,
                                               const int* __restrict__ batch,
                                               float* __restrict__ out,
                                               const float* __restrict__ bl) {
    int warp = (blockIdx.x * blockDim.x + threadIdx.x) >> 5;
    int lane = threadIdx.x & 31;
    int half = lane >> 4;
    int sub = lane & 15;
    int node = warp * 2 + half;

    if (node < NN) {
        const uint4* T = (const uint4*)g_t;
        float di = g_dinv[node];

        float acc[8];
        {
            uint4 u = T[(size_t)node * 16 + sub];   // self term t'[i]
            const __half2* p = (const __half2*)&u;
#pragma unroll
            for (int q = 0; q < 4; q++) {
                float2 f = __half22float2(p[q]);
                acc[q * 2] = f.x; acc[q * 2 + 1] = f.y;
            }
        }

        int e  = g_rowptr[node] + g_part[node >> 10];
        int e1 = (node + 1 < NN) ? (g_rowptr[node + 1] + g_part[(node + 1) >> 10]) : EE;

        for (; e + 8 <= e1; e += 8) {
            int s[8];
            uint4 v[8];
#pragma unroll
            for (int j = 0; j < 8; j++) s[j] = __ldg(&g_col[e + j]);
#pragma unroll
            for (int j = 0; j < 8; j++) v[j] = T[(size_t)s[j] * 16 + sub];
#pragma unroll
            for (int j = 0; j < 8; j++) {
                const __half2* p = (const __half2*)&v[j];
#pragma unroll
                for (int q = 0; q < 4; q++) {
                    float2 f = __half22float2(p[q]);
                    acc[q * 2] += f.x; acc[q * 2 + 1] += f.y;
                }
            }
        }
        for (; e + 4 <= e1; e += 4) {
            int s[4];
            uint4 v[4];
#pragma unroll
            for (int j = 0; j < 4; j++) s[j] = __ldg(&g_col[e + j]);
#pragma unroll
            for (int j = 0; j < 4; j++) v[j] = T[(size_t)s[j] * 16 + sub];
#pragma unroll
            for (int j = 0; j < 4; j++) {
                const __half2* p = (const __half2*)&v[j];
#pragma unroll
                for (int q = 0; q < 4; q++) {
                    float2 f = __half22float2(p[q]);
                    acc[q * 2] += f.x; acc[q * 2 + 1] += f.y;
                }
            }
        }
        for (; e < e1; ++e) {
            int s = __ldg(&g_col[e]);
            uint4 v = T[(size_t)s * 16 + sub];
            const __half2* p = (const __half2*)&v;
#pragma unroll
            for (int q = 0; q < 4; q++) {
                float2 f = __half22float2(p[q]);
                acc[q * 2] += f.x; acc[q * 2 + 1] += f.y;
            }
        }

        float4 be0 = ((const float4*)beta)[sub * 2];
        float4 be1v = ((const float4*)beta)[sub * 2 + 1];
        float y[8];
        y[0] = fmaxf(0.f, fmaf(di, acc[0], be0.x));
        y[1] = fmaxf(0.f, fmaf(di, acc[1], be0.y));
        y[2] = fmaxf(0.f, fmaf(di, acc[2], be0.z));
        y[3] = fmaxf(0.f, fmaf(di, acc[3], be0.w));
        y[4] = fmaxf(0.f, fmaf(di, acc[4], be1v.x));
        y[5] = fmaxf(0.f, fmaf(di, acc[5], be1v.y));
        y[6] = fmaxf(0.f, fmaf(di, acc[6], be1v.z));
        y[7] = fmaxf(0.f, fmaf(di, acc[7], be1v.w));

        if (!FINAL) {
            uint4 o;
            __half2* p = (__half2*)&o;
            p[0] = __floats2half2_rn(y[0], y[1]);
            p[1] = __floats2half2_rn(y[2], y[3]);
            p[2] = __floats2half2_rn(y[4], y[5]);
            p[3] = __floats2half2_rn(y[6], y[7]);
            ((uint4*)g_h)[(size_t)node * 16 + sub] = o;
        } else {
            float4 wl0 = ((const float4*)Wl)[sub * 2];
            float4 wl1 = ((const float4*)Wl)[sub * 2 + 1];
            float s = y[0] * wl0.x + y[1] * wl0.y + y[2] * wl0.z + y[3] * wl0.w +
                      y[4] * wl1.x + y[5] * wl1.y + y[6] * wl1.z + y[7] * wl1.w;
            unsigned mask = half ? 0xFFFF0000u : 0x0000FFFFu;
#pragma unroll
            for (int off = 8; off > 0; off >>= 1)
                s += __shfl_xor_sync(mask, s, off);
            if (sub == 0) atomicAdd(&g_gsum[batch[node]], s);
        }
    }

    if (FINAL) {
        // last-block-done: final block computes the pooled linear output
        __shared__ int sh_last;
        __syncthreads();
        if (threadIdx.x == 0) {
            __threadfence();
            int prev = atomicAdd(&g_done, 1);
            sh_last = (prev == (int)gridDim.x - 1) ? 1 : 0;
        }
        __syncthreads();
        if (sh_last) {
            float bb = bl[0];
            for (int g = threadIdx.x; g < GG; g += blockDim.x)
                out[g] = g_gsum[g] / fmaxf((float)g_gcnt[g], 1.0f) + bb;
        }
    }
}

// ---------------- host launcher --------------------------------------------
extern "C" void kernel_launch(void* const* d_in, const int* in_sizes, int n_in,
                              void* d_out, int out_size) {
    const float* x     = (const float*)d_in[0];
    const int*   ei    = (const int*)d_in[1];
    const int*   batch = (const int*)d_in[2];
    const float* W1 = (const float*)d_in[3];
    const float* b1 = (const float*)d_in[4];
    const float* g1 = (const float*)d_in[5];
    const float* be1 = (const float*)d_in[6];
    const float* m1 = (const float*)d_in[7];
    const float* v1 = (const float*)d_in[8];
    const float* W2 = (const float*)d_in[9];
    const float* b2 = (const float*)d_in[10];
    const float* g2 = (const float*)d_in[11];
    const float* be2 = (const float*)d_in[12];
    const float* m2 = (const float*)d_in[13];
    const float* v2 = (const float*)d_in[14];
    const float* W3 = (const float*)d_in[15];
    const float* b3 = (const float*)d_in[16];
    const float* g3 = (const float*)d_in[17];
    const float* be3 = (const float*)d_in[18];
    const float* m3 = (const float*)d_in[19];
    const float* v3 = (const float*)d_in[20];
    const float* Wl = (const float*)d_in[21];
    const float* bl = (const float*)d_in[22];

    __half *t, *h, *Wh;
    float *beta;
    cudaGetSymbolAddress((void**)&t, g_t);
    cudaGetSymbolAddress((void**)&h, g_h);
    cudaGetSymbolAddress((void**)&Wh, g_Wh);
    cudaGetSymbolAddress((void**)&beta, g_beta);

    const int GEMM_SMEM = 2 * 128 * 136 * (int)sizeof(__half);   // 69632
    cudaFuncSetAttribute(k_gemm_tc<true>,  cudaFuncAttributeMaxDynamicSharedMemorySize, GEMM_SMEM);
    cudaFuncSetAttribute(k_gemm_tc<false>, cudaFuncAttributeMaxDynamicSharedMemorySize, GEMM_SMEM);

    static cudaStream_t s1 = nullptr;
    static cudaEvent_t evStart = nullptr, evDinv = nullptr, evG1 = nullptr;
    if (s1 == nullptr) {
        cudaStreamCreateWithFlags(&s1, cudaStreamNonBlocking);
        cudaEventCreateWithFlags(&evStart, cudaEventDisableTiming);
        cudaEventCreateWithFlags(&evDinv, cudaEventDisableTiming);
        cudaEventCreateWithFlags(&evG1, cudaEventDisableTiming);
    }

    const int TPB = 256;
    const int GEMM_BLOCKS = (NN + 127) / 128;                    // 782
    const int AGG_BLOCKS = ((NN + 1) / 2 * 32 + TPB - 1) / TPB;  // 6250

    // ---- fork: side stream handles weight prep (input-only dependency)
    cudaEventRecord(evStart, 0);
    cudaStreamWaitEvent(s1, evStart, 0);
    {
        dim3 grid(64, 3);
        k_prep_w<<<grid, 256, 0, s1>>>(W1, W2, W3, b1, b2, b3, g1, g2, g3,
                                       be1, be2, be3, m1, m2, m3, v1, v2, v3);
    }

    // ---- main stream: graph preprocessing (scan_add eliminated)
    k_zero<<<(NN + TPB - 1) / TPB, TPB>>>();
    k_hist<<<(EE + TPB - 1) / TPB, TPB>>>(ei, batch);
    k_scan_local<<<NB, SCAN_B>>>();                     // produces dinv + local scan
    cudaEventRecord(evDinv, 0);
    k_scan_part<<<1, 128>>>();
    k_fill<<<(EE + TPB - 1) / TPB, TPB>>>(ei);

    // ---- side stream: gemm1 (needs Wh + dinv), overlaps scan/fill
    cudaStreamWaitEvent(s1, evDinv, 0);
    k_gemm_tc<true><<<GEMM_BLOCKS, 256, GEMM_SMEM, s1>>>(x, Wh, t);
    cudaEventRecord(evG1, s1);

    // ---- join, then layers (serial on main stream)
    cudaStreamWaitEvent(0, evG1, 0);
    k_agg16<false><<<AGG_BLOCKS, TPB>>>(beta, nullptr, nullptr, nullptr, nullptr);
    k_gemm_tc<false><<<GEMM_BLOCKS, 256, GEMM_SMEM>>>(h, Wh + HH * HH, t);
    k_agg16<false><<<AGG_BLOCKS, TPB>>>(beta + HH, nullptr, nullptr, nullptr, nullptr);
    k_gemm_tc<false><<<GEMM_BLOCKS, 256, GEMM_SMEM>>>(h, Wh + 2 * HH * HH, t);
    // layer-3 agg + mean-pool + linear head + output (fused k_final)
    k_agg16<true><<<AGG_BLOCKS, TPB>>>(beta + 2 * HH, Wl, batch, (float*)d_out, bl);
}

// round 12
// speedup vs baseline: 1.2412x; 1.0914x over previous
#include <cuda_runtime.h>
#include <cuda_fp16.h>
#include <cstdint>

#define NN 100000
#define EE 1600000
#define HH 128
#define GG 512
#define BN_EPS 1e-5f
#define SCAN_B 1024
#define NB ((NN + SCAN_B - 1) / SCAN_B)   // 98 scan blocks

// ---------------- scratch (device globals: no allocation allowed) -----------
__device__ __half g_t[(size_t)NN * HH];   // GEMM output t' = dinv .* (h @ W') (fp16)
__device__ __half g_h[(size_t)NN * HH];   // activated hidden (fp16)
__device__ __half g_Wh[3 * HH * HH];      // BN-folded fp16 weights
__device__ float  g_beta[3 * HH];         // BN-folded shifts
__device__ float  g_dinv[NN];
__device__ int    g_deg[NN];
__device__ int    g_rowptr[NN + 1];
__device__ int    g_cursor[NN];
__device__ int    g_col[EE];
__device__ float  g_gsum[GG];
__device__ int    g_gcnt[GG];
__device__ int    g_part[NB];

__device__ __forceinline__ uint32_t s2u(const void* p) {
    return (uint32_t)__cvta_generic_to_shared(p);
}

// ---------------- preprocessing kernels ------------------------------------
__global__ void k_zero() {
    int i = blockIdx.x * blockDim.x + threadIdx.x;
    if (i < NN) g_deg[i] = 0;
    if (i < GG) { g_gsum[i] = 0.0f; g_gcnt[i] = 0; }
}

__global__ void k_hist(const int* __restrict__ ei, const int* __restrict__ batch) {
    int e = blockIdx.x * blockDim.x + threadIdx.x;
    if (e < EE) atomicAdd(&g_deg[ei[EE + e]], 1);
    if (e < NN) atomicAdd(&g_gcnt[batch[e]], 1);
}

__global__ void k_scan_local() {
    __shared__ int sh[SCAN_B];
    int tx = threadIdx.x;
    int i = blockIdx.x * SCAN_B + tx;
    int v = (i < NN) ? g_deg[i] : 0;
    if (i < NN) g_dinv[i] = rsqrtf((float)(v + 1));   // fused dinv (+1 self-loop)
    sh[tx] = v;
    __syncthreads();
    for (int off = 1; off < SCAN_B; off <<= 1) {
        int t = (tx >= off) ? sh[tx - off] : 0;
        __syncthreads();
        sh[tx] += t;
        __syncthreads();
    }
    if (i < NN) g_rowptr[i] = sh[tx] - v;        // exclusive
    if (tx == SCAN_B - 1) g_part[blockIdx.x] = sh[tx];
}

__global__ void k_scan_part() {
    __shared__ int sh[128];
    int tx = threadIdx.x;
    int v = (tx < NB) ? g_part[tx] : 0;
    sh[tx] = v;
    __syncthreads();
    for (int off = 1; off < 128; off <<= 1) {
        int t = (tx >= off) ? sh[tx - off] : 0;
        __syncthreads();
        sh[tx] += t;
        __syncthreads();
    }
    if (tx < NB) g_part[tx] = sh[tx] - v;        // exclusive block offsets
}

__global__ void k_scan_add() {
    int i = blockIdx.x * blockDim.x + threadIdx.x;
    if (i < NN) {
        int v = g_rowptr[i] + g_part[i >> 10];
        g_rowptr[i] = v;
        g_cursor[i] = v;
    }
    if (i == 0) g_rowptr[NN] = EE;
}

__global__ void k_fill(const int* __restrict__ ei) {
    int e = blockIdx.x * blockDim.x + threadIdx.x;
    if (e < EE) {
        int src = ei[e];
        int dst = ei[EE + e];
        int p = atomicAdd(&g_cursor[dst], 1);
        g_col[p] = src;
    }
}

// Fold BN scale into W columns (fp16) for all 3 layers, compute folded shifts.
__global__ void k_prep_w(const float* __restrict__ W1v, const float* __restrict__ W2v,
                         const float* __restrict__ W3v,
                         const float* __restrict__ b1v, const float* __restrict__ b2v,
                         const float* __restrict__ b3v,
                         const float* __restrict__ ga1, const float* __restrict__ ga2,
                         const float* __restrict__ ga3,
                         const float* __restrict__ be1, const float* __restrict__ be2,
                         const float* __restrict__ be3,
                         const float* __restrict__ m1v, const float* __restrict__ m2v,
                         const float* __restrict__ m3v,
                         const float* __restrict__ v1v, const float* __restrict__ v2v,
                         const float* __restrict__ v3v) {
    int layer = blockIdx.y;
    const float* W  = layer == 0 ? W1v : layer == 1 ? W2v : W3v;
    const float* b  = layer == 0 ? b1v : layer == 1 ? b2v : b3v;
    const float* ga = layer == 0 ? ga1 : layer == 1 ? ga2 : ga3;
    const float* be = layer == 0 ? be1 : layer == 1 ? be2 : be3;
    const float* m  = layer == 0 ? m1v : layer == 1 ? m2v : m3v;
    const float* v  = layer == 0 ? v1v : layer == 1 ? v2v : v3v;
    int idx = blockIdx.x * blockDim.x + threadIdx.x;
    if (idx < HH * HH) {
        int n = idx & (HH - 1);
        float alpha = ga[n] * rsqrtf(v[n] + BN_EPS);
        g_Wh[layer * HH * HH + idx] = __float2half(W[idx] * alpha);
    }
    if (idx < HH) {
        float alpha = ga[idx] * rsqrtf(v[idx] + BN_EPS);
        g_beta[layer * HH + idx] = (b[idx] - m[idx]) * alpha + be[idx];
    }
}

// ---------------- fp16 tensor-core GEMM + dinv prescale epilogue -----------
// Y[i,:] = dinv[i] * (X[i,:] @ W).
// F32IN (layer 1): bulk sync loads (with f32->f16 convert); computes dinv
// directly from g_deg so it only depends on k_hist (overlaps the scan chain).
// !F32IN: cp.async 2-stage K-split; reads g_dinv.
template <bool F32IN>
__global__ void __launch_bounds__(256) k_gemm_tc(const void* __restrict__ Xv,
                                                 const __half* __restrict__ W,
                                                 __half* __restrict__ Y) {
    extern __shared__ __half sh[];
    __half* As = sh;               // 128 x 136 (272 B pitch)
    __half* Ws = sh + 128 * 136;   // 128 x 136 (row = k, cols = n)

    int tid = threadIdx.x;
    int row0 = blockIdx.x * 128;

    if (F32IN) {
        const uint4* Wg = (const uint4*)W;
#pragma unroll
        for (int i = 0; i < 8; i++) {
            int idx = i * 256 + tid;
            int r = idx >> 4, c = (idx & 15) * 8;
            *(uint4*)&Ws[r * 136 + c] = Wg[idx];
        }
        const float4* Xg = (const float4*)Xv;
#pragma unroll
        for (int i = 0; i < 16; i++) {
            int idx = i * 256 + tid;
            int r = idx >> 5, c = (idx & 31) * 4;
            float4 v = make_float4(0.f, 0.f, 0.f, 0.f);
            if (row0 + r < NN) v = Xg[(size_t)(row0 + r) * 32 + (idx & 31)];
            *(__half2*)&As[r * 136 + c]     = __floats2half2_rn(v.x, v.y);
            *(__half2*)&As[r * 136 + c + 2] = __floats2half2_rn(v.z, v.w);
        }
        __syncthreads();
    } else {
        const char* Ag = (const char*)Xv;     // 256 B per row (k bytes)
        const char* Wg = (const char*)W;      // 256 B per row (row = k, bytes = n)
#pragma unroll
        for (int h = 0; h < 2; h++) {
#pragma unroll
            for (int i = 0; i < 4; i++) {     // A: 1024 chunks
                int idx = i * 256 + tid;
                int r = idx >> 3, ch = idx & 7;
                uint32_t saddr = s2u(&As[0]) + r * 272 + h * 128 + ch * 16;
                const char* gaddr = Ag + (size_t)(row0 + r) * 256 + h * 128 + ch * 16;
                int sz = (row0 + r < NN) ? 16 : 0;
                asm volatile("cp.async.cg.shared.global [%0], [%1], 16, %2;"
                             :: "r"(saddr), "l"(gaddr), "r"(sz));
            }
#pragma unroll
            for (int i = 0; i < 4; i++) {     // W: 64 rows x 16 chunks
                int idx = i * 256 + tid;
                int r = h * 64 + (idx >> 4);
                int ch = idx & 15;
                uint32_t saddr = s2u(&Ws[0]) + r * 272 + ch * 16;
                const char* gaddr = Wg + (size_t)r * 256 + ch * 16;
                asm volatile("cp.async.cg.shared.global [%0], [%1], 16;"
                             :: "r"(saddr), "l"(gaddr));
            }
            asm volatile("cp.async.commit_group;");
        }
    }

    int wid = tid >> 5, lane = tid & 31;
    int m0 = wid * 16;

    float acc[16][4];
#pragma unroll
    for (int nt = 0; nt < 16; nt++)
#pragma unroll
        for (int c = 0; c < 4; c++) acc[nt][c] = 0.f;

#pragma unroll
    for (int h = 0; h < 2; h++) {
        if (!F32IN) {
            if (h == 0) { asm volatile("cp.async.wait_group 1;"); }
            else        { asm volatile("cp.async.wait_group 0;"); }
            __syncthreads();
        }
#pragma unroll
        for (int ksl = 0; ksl < 4; ksl++) {
            int ks = h * 4 + ksl;
            uint32_t a0, a1, a2, a3;
            uint32_t aaddr = s2u(&As[(m0 + (lane & 15)) * 136 + ks * 16 + (lane >> 4) * 8]);
            asm volatile("ldmatrix.sync.aligned.m8n8.x4.shared.b16 {%0,%1,%2,%3}, [%4];"
                         : "=r"(a0), "=r"(a1), "=r"(a2), "=r"(a3) : "r"(aaddr));
#pragma unroll
            for (int ng = 0; ng < 8; ng++) {
                uint32_t b0, b1, b2, b3;
                uint32_t baddr = s2u(&Ws[(ks * 16 + (lane & 15)) * 136 +
                                         ng * 16 + (lane >> 4) * 8]);
                asm volatile("ldmatrix.sync.aligned.m8n8.x4.trans.shared.b16 {%0,%1,%2,%3}, [%4];"
                             : "=r"(b0), "=r"(b1), "=r"(b2), "=r"(b3) : "r"(baddr));
                int nt = ng * 2;
                asm volatile(
                    "mma.sync.aligned.m16n8k16.row.col.f32.f16.f16.f32 "
                    "{%0,%1,%2,%3}, {%4,%5,%6,%7}, {%8,%9}, {%0,%1,%2,%3};"
                    : "+f"(acc[nt][0]), "+f"(acc[nt][1]), "+f"(acc[nt][2]), "+f"(acc[nt][3])
                    : "r"(a0), "r"(a1), "r"(a2), "r"(a3), "r"(b0), "r"(b1));
                asm volatile(
                    "mma.sync.aligned.m16n8k16.row.col.f32.f16.f16.f32 "
                    "{%0,%1,%2,%3}, {%4,%5,%6,%7}, {%8,%9}, {%0,%1,%2,%3};"
                    : "+f"(acc[nt + 1][0]), "+f"(acc[nt + 1][1]), "+f"(acc[nt + 1][2]), "+f"(acc[nt + 1][3])
                    : "r"(a0), "r"(a1), "r"(a2), "r"(a3), "r"(b2), "r"(b3));
            }
        }
    }

    int r0 = row0 + m0 + (lane >> 2);
    int cb = (lane & 3) * 2;
    float d0, d1;
    if (F32IN) {
        // dinv from degree directly -> no dependency on the scan chain
        d0 = (r0 < NN) ? rsqrtf((float)(g_deg[r0] + 1)) : 0.f;
        d1 = (r0 + 8 < NN) ? rsqrtf((float)(g_deg[r0 + 8] + 1)) : 0.f;
    } else {
        d0 = (r0 < NN) ? g_dinv[r0] : 0.f;
        d1 = (r0 + 8 < NN) ? g_dinv[r0 + 8] : 0.f;
    }
#pragma unroll
    for (int nt = 0; nt < 16; nt++) {
        if (r0 < NN)
            *(__half2*)&Y[(size_t)r0 * 128 + nt * 8 + cb] =
                __floats2half2_rn(acc[nt][0] * d0, acc[nt][1] * d0);
        if (r0 + 8 < NN)
            *(__half2*)&Y[(size_t)(r0 + 8) * 128 + nt * 8 + cb] =
                __floats2half2_rn(acc[nt][2] * d1, acc[nt][3] * d1);
    }
}

// ---------------- aggregation + folded-BN + ReLU (2 nodes per warp) --------
// 16 lanes x uint4 (LDG.128) per node row. t' pre-scaled by dinv[src].
template <bool FINAL>
__global__ void __launch_bounds__(256) k_agg16(const float* __restrict__ beta,
                                               const float* __restrict__ Wl,
                                               const int* __restrict__ batch) {
    int warp = (blockIdx.x * blockDim.x + threadIdx.x) >> 5;
    int lane = threadIdx.x & 31;
    int half = lane >> 4;
    int sub = lane & 15;
    int node = warp * 2 + half;
    if (node >= NN) return;

    const uint4* T = (const uint4*)g_t;   // 16 x uint4 (8 halves) per row
    float di = g_dinv[node];

    float acc[8];
    {
        uint4 u = T[(size_t)node * 16 + sub];   // self term t'[i]
        const __half2* p = (const __half2*)&u;
#pragma unroll
        for (int q = 0; q < 4; q++) {
            float2 f = __half22float2(p[q]);
            acc[q * 2] = f.x; acc[q * 2 + 1] = f.y;
        }
    }

    int e = g_rowptr[node];
    int e1 = g_rowptr[node + 1];

    for (; e + 8 <= e1; e += 8) {
        int s[8];
        uint4 v[8];
#pragma unroll
        for (int j = 0; j < 8; j++) s[j] = __ldg(&g_col[e + j]);
#pragma unroll
        for (int j = 0; j < 8; j++) v[j] = T[(size_t)s[j] * 16 + sub];
#pragma unroll
        for (int j = 0; j < 8; j++) {
            const __half2* p = (const __half2*)&v[j];
#pragma unroll
            for (int q = 0; q < 4; q++) {
                float2 f = __half22float2(p[q]);
                acc[q * 2] += f.x; acc[q * 2 + 1] += f.y;
            }
        }
    }
    for (; e + 4 <= e1; e += 4) {
        int s[4];
        uint4 v[4];
#pragma unroll
        for (int j = 0; j < 4; j++) s[j] = __ldg(&g_col[e + j]);
#pragma unroll
        for (int j = 0; j < 4; j++) v[j] = T[(size_t)s[j] * 16 + sub];
#pragma unroll
        for (int j = 0; j < 4; j++) {
            const __half2* p = (const __half2*)&v[j];
#pragma unroll
            for (int q = 0; q < 4; q++) {
                float2 f = __half22float2(p[q]);
                acc[q * 2] += f.x; acc[q * 2 + 1] += f.y;
            }
        }
    }
    for (; e < e1; ++e) {
        int s = __ldg(&g_col[e]);
        uint4 v = T[(size_t)s * 16 + sub];
        const __half2* p = (const __half2*)&v;
#pragma unroll
        for (int q = 0; q < 4; q++) {
            float2 f = __half22float2(p[q]);
            acc[q * 2] += f.x; acc[q * 2 + 1] += f.y;
        }
    }

    float4 be0 = ((const float4*)beta)[sub * 2];
    float4 be1v = ((const float4*)beta)[sub * 2 + 1];
    float y[8];
    y[0] = fmaxf(0.f, fmaf(di, acc[0], be0.x));
    y[1] = fmaxf(0.f, fmaf(di, acc[1], be0.y));
    y[2] = fmaxf(0.f, fmaf(di, acc[2], be0.z));
    y[3] = fmaxf(0.f, fmaf(di, acc[3], be0.w));
    y[4] = fmaxf(0.f, fmaf(di, acc[4], be1v.x));
    y[5] = fmaxf(0.f, fmaf(di, acc[5], be1v.y));
    y[6] = fmaxf(0.f, fmaf(di, acc[6], be1v.z));
    y[7] = fmaxf(0.f, fmaf(di, acc[7], be1v.w));

    if (!FINAL) {
        uint4 o;
        __half2* p = (__half2*)&o;
        p[0] = __floats2half2_rn(y[0], y[1]);
        p[1] = __floats2half2_rn(y[2], y[3]);
        p[2] = __floats2half2_rn(y[4], y[5]);
        p[3] = __floats2half2_rn(y[6], y[7]);
        ((uint4*)g_h)[(size_t)node * 16 + sub] = o;
    } else {
        float4 wl0 = ((const float4*)Wl)[sub * 2];
        float4 wl1 = ((const float4*)Wl)[sub * 2 + 1];
        float s = y[0] * wl0.x + y[1] * wl0.y + y[2] * wl0.z + y[3] * wl0.w +
                  y[4] * wl1.x + y[5] * wl1.y + y[6] * wl1.z + y[7] * wl1.w;
        unsigned mask = half ? 0xFFFF0000u : 0x0000FFFFu;
#pragma unroll
        for (int off = 8; off > 0; off >>= 1)
            s += __shfl_xor_sync(mask, s, off);
        if (sub == 0) atomicAdd(&g_gsum[batch[node]], s);
    }
}

__global__ void k_final(float* __restrict__ out, const float* __restrict__ bl) {
    int g = blockIdx.x * blockDim.x + threadIdx.x;
    if (g < GG) out[g] = g_gsum[g] / fmaxf((float)g_gcnt[g], 1.0f) + bl[0];
}

// ---------------- host launcher --------------------------------------------
extern "C" void kernel_launch(void* const* d_in, const int* in_sizes, int n_in,
                              void* d_out, int out_size) {
    const float* x     = (const float*)d_in[0];
    const int*   ei    = (const int*)d_in[1];
    const int*   batch = (const int*)d_in[2];
    const float* W1 = (const float*)d_in[3];
    const float* b1 = (const float*)d_in[4];
    const float* g1 = (const float*)d_in[5];
    const float* be1 = (const float*)d_in[6];
    const float* m1 = (const float*)d_in[7];
    const float* v1 = (const float*)d_in[8];
    const float* W2 = (const float*)d_in[9];
    const float* b2 = (const float*)d_in[10];
    const float* g2 = (const float*)d_in[11];
    const float* be2 = (const float*)d_in[12];
    const float* m2 = (const float*)d_in[13];
    const float* v2 = (const float*)d_in[14];
    const float* W3 = (const float*)d_in[15];
    const float* b3 = (const float*)d_in[16];
    const float* g3 = (const float*)d_in[17];
    const float* be3 = (const float*)d_in[18];
    const float* m3 = (const float*)d_in[19];
    const float* v3 = (const float*)d_in[20];
    const float* Wl = (const float*)d_in[21];
    const float* bl = (const float*)d_in[22];

    __half *t, *h, *Wh;
    float *beta;
    cudaGetSymbolAddress((void**)&t, g_t);
    cudaGetSymbolAddress((void**)&h, g_h);
    cudaGetSymbolAddress((void**)&Wh, g_Wh);
    cudaGetSymbolAddress((void**)&beta, g_beta);

    const int GEMM_SMEM = 2 * 128 * 136 * (int)sizeof(__half);   // 69632
    cudaFuncSetAttribute(k_gemm_tc<true>,  cudaFuncAttributeMaxDynamicSharedMemorySize, GEMM_SMEM);
    cudaFuncSetAttribute(k_gemm_tc<false>, cudaFuncAttributeMaxDynamicSharedMemorySize, GEMM_SMEM);

    static cudaStream_t s1 = nullptr;
    static cudaEvent_t evStart = nullptr, evHist = nullptr, evG1 = nullptr;
    if (s1 == nullptr) {
        cudaStreamCreateWithFlags(&s1, cudaStreamNonBlocking);
        cudaEventCreateWithFlags(&evStart, cudaEventDisableTiming);
        cudaEventCreateWithFlags(&evHist, cudaEventDisableTiming);
        cudaEventCreateWithFlags(&evG1, cudaEventDisableTiming);
    }

    const int TPB = 256;
    const int GEMM_BLOCKS = (NN + 127) / 128;                    // 782
    const int AGG_BLOCKS = ((NN + 1) / 2 * 32 + TPB - 1) / TPB;  // 6250

    // ---- fork: side stream handles weight prep (input-only dependency)
    cudaEventRecord(evStart, 0);
    cudaStreamWaitEvent(s1, evStart, 0);
    {
        dim3 grid(64, 3);
        k_prep_w<<<grid, 256, 0, s1>>>(W1, W2, W3, b1, b2, b3, g1, g2, g3,
                                       be1, be2, be3, m1, m2, m3, v1, v2, v3);
    }

    // ---- main stream: graph preprocessing
    k_zero<<<(NN + TPB - 1) / TPB, TPB>>>();
    k_hist<<<(EE + TPB - 1) / TPB, TPB>>>(ei, batch);
    cudaEventRecord(evHist, 0);                         // gemm1 needs only g_deg
    k_scan_local<<<NB, SCAN_B>>>();                     // produces dinv + scan
    k_scan_part<<<1, 128>>>();
    k_scan_add<<<(NN + TPB) / TPB, TPB>>>();
    k_fill<<<(EE + TPB - 1) / TPB, TPB>>>(ei);

    // ---- side stream: gemm1 (needs Wh + deg), overlaps the whole scan chain
    cudaStreamWaitEvent(s1, evHist, 0);
    k_gemm_tc<true><<<GEMM_BLOCKS, 256, GEMM_SMEM, s1>>>(x, Wh, t);
    cudaEventRecord(evG1, s1);

    // ---- join, then layers (serial on main stream)
    cudaStreamWaitEvent(0, evG1, 0);
    k_agg16<false><<<AGG_BLOCKS, TPB>>>(beta, nullptr, nullptr);
    k_gemm_tc<false><<<GEMM_BLOCKS, 256, GEMM_SMEM>>>(h, Wh + HH * HH, t);
    k_agg16<false><<<AGG_BLOCKS, TPB>>>(beta + HH, nullptr, nullptr);
    k_gemm_tc<false><<<GEMM_BLOCKS, 256, GEMM_SMEM>>>(h, Wh + 2 * HH * HH, t);
    k_agg16<true><<<AGG_BLOCKS, TPB>>>(beta + 2 * HH, Wl, batch);

    k_final<<<(GG + TPB - 1) / TPB, TPB>>>((float*)d_out, bl);
}